// round 1
// baseline (speedup 1.0000x reference)
#include <cuda_runtime.h>
#include <cstdint>

// Problem constants (fixed by the dataset)
#define B_   8
#define T_   1024
#define Cc_  1024
#define H_   16
#define D_   64
#define BH_  (B_*H_)     // 128
#define M_   (B_*T_)     // 8192
#define N3_  3072

// Scratch (static device globals: allocation-free)
__device__ float g_Q[(size_t)BH_*T_*D_];   // [B*H, T, D]
__device__ float g_K[(size_t)BH_*T_*D_];
__device__ float g_V[(size_t)BH_*T_*D_];
__device__ float g_O[(size_t)M_*Cc_];      // attention output, [B*T, C]

// ---------------------------------------------------------------------------
// SGEMM: 128x128 tile, BK=8, 256 threads, 8x8 per-thread microtile.
// MODE 1: A = x, C written as split Q/K/V in [B,H,T,D] layout (+bias)
// MODE 0: A = g_O (internal), C = plain [M,N] output (+bias)
// All dims divisible by tile sizes -> no bounds checks.
// ---------------------------------------------------------------------------
template<int MODE>
__global__ __launch_bounds__(256)
void sgemm_kernel(const float* __restrict__ A,
                  const float* __restrict__ Bm,
                  const float* __restrict__ bias,
                  float* __restrict__ Cout,
                  int M, int N, int K)
{
    __shared__ float As[8][128];   // transposed A tile: As[k][m]
    __shared__ float Bs[8][128];   // Bs[k][n]

    const int tid = threadIdx.x;
    const int bx = blockIdx.x, by = blockIdx.y;
    const int tx = tid & 15, ty = tid >> 4;

    const float* Ain = (MODE == 0) ? (const float*)g_O : A;

    const int arow = tid >> 1;            // 0..127
    const int acol = (tid & 1) << 2;      // 0 or 4
    const int brow = tid >> 5;            // 0..7
    const int bcol = (tid & 31) << 2;     // 0..124

    const float* Aptr = Ain + (size_t)(by*128 + arow)*K + acol;
    const float* Bptr = Bm  + (size_t)brow*N + bx*128 + bcol;

    float acc[8][8];
#pragma unroll
    for (int i = 0; i < 8; i++)
#pragma unroll
        for (int j = 0; j < 8; j++) acc[i][j] = 0.f;

    for (int k0 = 0; k0 < K; k0 += 8) {
        float4 a = *(const float4*)(Aptr + k0);
        float4 b = *(const float4*)(Bptr + (size_t)k0*N);
        As[acol+0][arow] = a.x; As[acol+1][arow] = a.y;
        As[acol+2][arow] = a.z; As[acol+3][arow] = a.w;
        *(float4*)&Bs[brow][bcol] = b;
        __syncthreads();
#pragma unroll
        for (int k = 0; k < 8; ++k) {
            float4 a0 = *(const float4*)&As[k][ty*8];
            float4 a1 = *(const float4*)&As[k][ty*8+4];
            float4 b0 = *(const float4*)&Bs[k][tx*8];
            float4 b1 = *(const float4*)&Bs[k][tx*8+4];
            float av[8] = {a0.x,a0.y,a0.z,a0.w,a1.x,a1.y,a1.z,a1.w};
            float bv[8] = {b0.x,b0.y,b0.z,b0.w,b1.x,b1.y,b1.z,b1.w};
#pragma unroll
            for (int i = 0; i < 8; i++)
#pragma unroll
                for (int j = 0; j < 8; j++)
                    acc[i][j] = fmaf(av[i], bv[j], acc[i][j]);
        }
        __syncthreads();
    }

    const int row0 = by*128 + ty*8;
    const int col0 = bx*128 + tx*8;
    float bv[8];
#pragma unroll
    for (int j = 0; j < 8; j++) bv[j] = bias[col0 + j];

    if (MODE == 0) {
#pragma unroll
        for (int i = 0; i < 8; i++) {
            float* cp = Cout + (size_t)(row0 + i)*N + col0;
            *(float4*)(cp)   = make_float4(acc[i][0]+bv[0], acc[i][1]+bv[1],
                                           acc[i][2]+bv[2], acc[i][3]+bv[3]);
            *(float4*)(cp+4) = make_float4(acc[i][4]+bv[4], acc[i][5]+bv[5],
                                           acc[i][6]+bv[6], acc[i][7]+bv[7]);
        }
    } else {
        // col0 in [0,3072): segment (q/k/v), head, dim. A 128-wide tile never
        // crosses a segment (1024%128==0) and an 8-wide thread chunk never
        // crosses a head (64%8==0) -> stores stay contiguous float4s.
        const int seg = col0 >> 10;
        const int c   = col0 & 1023;
        const int h   = c >> 6;
        const int d   = c & 63;
        float* dst = (seg == 0) ? g_Q : (seg == 1) ? g_K : g_V;
#pragma unroll
        for (int i = 0; i < 8; i++) {
            int r = row0 + i;
            int b = r >> 10, t = r & 1023;
            float* cp = dst + (((size_t)(b*H_ + h))*T_ + t)*D_ + d;
            *(float4*)(cp)   = make_float4(acc[i][0]+bv[0], acc[i][1]+bv[1],
                                           acc[i][2]+bv[2], acc[i][3]+bv[3]);
            *(float4*)(cp+4) = make_float4(acc[i][4]+bv[4], acc[i][5]+bv[5],
                                           acc[i][6]+bv[6], acc[i][7]+bv[7]);
        }
    }
}

// ---------------------------------------------------------------------------
// Flash attention, fp32. Block = 64 q-rows x full head. 256 threads (16x16),
// 4x4 S fragment per thread, online softmax, causal tile skipping.
// Smem: Qs[64][68] (natural), KPs[64][68] (K transposed [d][c], then reused
// for P [r][c]), Vs[64][68] (natural). 52,224 B dynamic.
// ---------------------------------------------------------------------------
#define SMEM_ATTN (3*64*68*4)

__global__ __launch_bounds__(256)
void attn_kernel()
{
    extern __shared__ float sm[];
    float (*Qs)[68]  = (float (*)[68])(sm);
    float (*KPs)[68] = (float (*)[68])(sm + 64*68);
    float (*Vs)[68]  = (float (*)[68])(sm + 2*64*68);

    const int tid = threadIdx.x;
    const int tx = tid & 15, ty = tid >> 4;
    const int qt = blockIdx.x;        // q tile (0..15)
    const int bh = blockIdx.y;        // batch*head (0..127)

    const float* Qg = g_Q + ((size_t)bh*T_ + qt*64)*D_;
    for (int idx = tid; idx < 64*16; idx += 256) {
        int r = idx >> 4, c4 = (idx & 15) << 2;
        *(float4*)&Qs[r][c4] = *(const float4*)(Qg + (size_t)r*D_ + c4);
    }

    float m_i[4], l_i[4], Oa[4][4];
#pragma unroll
    for (int i = 0; i < 4; i++) {
        m_i[i] = -1e30f; l_i[i] = 0.f;
#pragma unroll
        for (int j = 0; j < 4; j++) Oa[i][j] = 0.f;
    }

    for (int kt = 0; kt <= qt; ++kt) {
        const float* Kg = g_K + ((size_t)bh*T_ + kt*64)*D_;
        const float* Vg = g_V + ((size_t)bh*T_ + kt*64)*D_;

        // K transposed into KPs[d][c]; c fast across threads -> conflict-free STS
        for (int idx = tid; idx < 1024; idx += 256) {
            int c = idx & 63, d4 = (idx >> 6) << 2;
            float4 kv = *(const float4*)(Kg + (size_t)c*D_ + d4);
            KPs[d4+0][c] = kv.x; KPs[d4+1][c] = kv.y;
            KPs[d4+2][c] = kv.z; KPs[d4+3][c] = kv.w;
        }
        for (int idx = tid; idx < 1024; idx += 256) {
            int r = idx >> 4, c4 = (idx & 15) << 2;
            *(float4*)&Vs[r][c4] = *(const float4*)(Vg + (size_t)r*D_ + c4);
        }
        __syncthreads();

        // S = Q K^T (raw)
        float s[4][4];
#pragma unroll
        for (int i = 0; i < 4; i++)
#pragma unroll
            for (int j = 0; j < 4; j++) s[i][j] = 0.f;

#pragma unroll 4
        for (int d = 0; d < 64; d += 4) {
            float qv[4][4], kv[4][4];
#pragma unroll
            for (int i = 0; i < 4; i++) {
                float4 t = *(const float4*)&Qs[ty*4+i][d];
                qv[i][0] = t.x; qv[i][1] = t.y; qv[i][2] = t.z; qv[i][3] = t.w;
            }
#pragma unroll
            for (int k = 0; k < 4; k++) {
                float4 t = *(const float4*)&KPs[d+k][tx*4];
                kv[k][0] = t.x; kv[k][1] = t.y; kv[k][2] = t.z; kv[k][3] = t.w;
            }
#pragma unroll
            for (int i = 0; i < 4; i++)
#pragma unroll
                for (int j = 0; j < 4; j++)
                    s[i][j] += qv[i][0]*kv[0][j] + qv[i][1]*kv[1][j]
                             + qv[i][2]*kv[2][j] + qv[i][3]*kv[3][j];
        }

        // scale + causal mask (only diagonal tile needs masking)
        const bool diag = (kt == qt);
#pragma unroll
        for (int i = 0; i < 4; i++)
#pragma unroll
            for (int j = 0; j < 4; j++) {
                float v = s[i][j] * 0.125f;   // 1/sqrt(64)
                if (diag && (tx*4 + j) > (ty*4 + i)) v = -1e30f;
                s[i][j] = v;
            }

        // online softmax: row = 16 threads (same ty) = one 16-lane half-warp
#pragma unroll
        for (int i = 0; i < 4; i++) {
            float mx = fmaxf(fmaxf(s[i][0], s[i][1]), fmaxf(s[i][2], s[i][3]));
            mx = fmaxf(mx, __shfl_xor_sync(0xffffffffu, mx, 8));
            mx = fmaxf(mx, __shfl_xor_sync(0xffffffffu, mx, 4));
            mx = fmaxf(mx, __shfl_xor_sync(0xffffffffu, mx, 2));
            mx = fmaxf(mx, __shfl_xor_sync(0xffffffffu, mx, 1));
            float mnew  = fmaxf(m_i[i], mx);
            float alpha = __expf(m_i[i] - mnew);
            float rs = 0.f;
#pragma unroll
            for (int j = 0; j < 4; j++) { s[i][j] = __expf(s[i][j] - mnew); rs += s[i][j]; }
            rs += __shfl_xor_sync(0xffffffffu, rs, 8);
            rs += __shfl_xor_sync(0xffffffffu, rs, 4);
            rs += __shfl_xor_sync(0xffffffffu, rs, 2);
            rs += __shfl_xor_sync(0xffffffffu, rs, 1);
            l_i[i] = l_i[i]*alpha + rs;
            m_i[i] = mnew;
#pragma unroll
            for (int j = 0; j < 4; j++) Oa[i][j] *= alpha;
        }

        __syncthreads();                 // all K reads done; KPs becomes P
#pragma unroll
        for (int i = 0; i < 4; i++)
            *(float4*)&KPs[ty*4+i][tx*4] = make_float4(s[i][0], s[i][1], s[i][2], s[i][3]);
        __syncthreads();

        // O += P @ V
#pragma unroll 4
        for (int c = 0; c < 64; c += 4) {
            float pv[4][4], vv[4][4];
#pragma unroll
            for (int i = 0; i < 4; i++) {
                float4 t = *(const float4*)&KPs[ty*4+i][c];
                pv[i][0] = t.x; pv[i][1] = t.y; pv[i][2] = t.z; pv[i][3] = t.w;
            }
#pragma unroll
            for (int k = 0; k < 4; k++) {
                float4 t = *(const float4*)&Vs[c+k][tx*4];
                vv[k][0] = t.x; vv[k][1] = t.y; vv[k][2] = t.z; vv[k][3] = t.w;
            }
#pragma unroll
            for (int i = 0; i < 4; i++)
#pragma unroll
                for (int j = 0; j < 4; j++)
                    Oa[i][j] += pv[i][0]*vv[0][j] + pv[i][1]*vv[1][j]
                              + pv[i][2]*vv[2][j] + pv[i][3]*vv[3][j];
        }
        __syncthreads();                 // before next tile overwrites KPs/Vs
    }

    // normalize + write [B,T,C] (un-transpose heads)
    const int b = bh >> 4, h = bh & 15;
#pragma unroll
    for (int i = 0; i < 4; i++) {
        float inv = 1.f / l_i[i];
        float* Op = g_O + ((size_t)(b*T_ + qt*64 + ty*4 + i))*Cc_ + h*64 + tx*4;
        *(float4*)Op = make_float4(Oa[i][0]*inv, Oa[i][1]*inv, Oa[i][2]*inv, Oa[i][3]*inv);
    }
}

// ---------------------------------------------------------------------------
extern "C" void kernel_launch(void* const* d_in, const int* in_sizes, int n_in,
                              void* d_out, int out_size)
{
    const float* x    = (const float*)d_in[0];
    const float* Wqkv = (const float*)d_in[1];
    const float* bqkv = (const float*)d_in[2];
    const float* Wout = (const float*)d_in[3];
    const float* bout = (const float*)d_in[4];
    float* out = (float*)d_out;

    cudaFuncSetAttribute(attn_kernel,
                         cudaFuncAttributeMaxDynamicSharedMemorySize, SMEM_ATTN);

    // 1) QKV projection, scattered to [B,H,T,D] Q/K/V
    dim3 g1(N3_/128, M_/128);
    sgemm_kernel<1><<<g1, 256>>>(x, Wqkv, bqkv, nullptr, M_, N3_, Cc_);

    // 2) causal flash attention -> g_O [B,T,C]
    attn_kernel<<<dim3(T_/64, BH_), 256, SMEM_ATTN>>>();

    // 3) output projection -> d_out
    dim3 g3(Cc_/128, M_/128);
    sgemm_kernel<0><<<g3, 256>>>(nullptr, Wout, bout, out, M_, Cc_, Cc_);
}

// round 3
// speedup vs baseline: 1.3221x; 1.3221x over previous
#include <cuda_runtime.h>
#include <cuda_bf16.h>
#include <cstdint>

// Problem constants
#define B_   8
#define T_   1024
#define Cc_  1024
#define H_   16
#define D_   64
#define BH_  (B_*H_)     // 128
#define M_   (B_*T_)     // 8192
#define N3_  3072

// Scratch (static device globals: allocation-free)
__device__ float g_Q[(size_t)BH_*T_*D_];   // [B*H, T, D]
__device__ float g_K[(size_t)BH_*T_*D_];
__device__ float g_V[(size_t)BH_*T_*D_];
__device__ float g_O[(size_t)M_*Cc_];      // attention output, [B*T, C]

// ---------------------------------------------------------------------------
__device__ __forceinline__ uint32_t smem_u32(const void* p) {
    uint32_t a;
    asm("{ .reg .u64 t; cvta.to.shared.u64 t, %1; cvt.u32.u64 %0, t; }"
        : "=r"(a) : "l"(p));
    return a;
}

__device__ __forceinline__ void ldsm_x4(uint32_t& r0, uint32_t& r1,
                                        uint32_t& r2, uint32_t& r3, uint32_t addr) {
    asm volatile("ldmatrix.sync.aligned.m8n8.x4.shared.b16 {%0,%1,%2,%3}, [%4];"
                 : "=r"(r0), "=r"(r1), "=r"(r2), "=r"(r3) : "r"(addr));
}

__device__ __forceinline__ void mma_bf16(float* d, uint32_t a0, uint32_t a1,
                                         uint32_t a2, uint32_t a3,
                                         uint32_t b0, uint32_t b1) {
    asm volatile(
        "mma.sync.aligned.m16n8k16.row.col.f32.bf16.bf16.f32 "
        "{%0,%1,%2,%3}, {%4,%5,%6,%7}, {%8,%9}, {%0,%1,%2,%3};"
        : "+f"(d[0]), "+f"(d[1]), "+f"(d[2]), "+f"(d[3])
        : "r"(a0), "r"(a1), "r"(a2), "r"(a3), "r"(b0), "r"(b1));
}

// bf16 split: v = hi + lo (each exact bf16); 3-pass MMA drops lo*lo (~2^-16)
__device__ __forceinline__ void split4_bf16(float4 v, uint2& hi, uint2& lo) {
    float f[4] = {v.x, v.y, v.z, v.w};
    unsigned short h[4], l[4];
#pragma unroll
    for (int i = 0; i < 4; i++) {
        __nv_bfloat16 hb = __float2bfloat16(f[i]);
        float r = f[i] - __bfloat162float(hb);
        __nv_bfloat16 lb = __float2bfloat16(r);
        h[i] = __bfloat16_as_ushort(hb);
        l[i] = __bfloat16_as_ushort(lb);
    }
    hi = make_uint2((uint32_t)h[0] | ((uint32_t)h[1] << 16),
                    (uint32_t)h[2] | ((uint32_t)h[3] << 16));
    lo = make_uint2((uint32_t)l[0] | ((uint32_t)l[1] << 16),
                    (uint32_t)l[2] | ((uint32_t)l[3] << 16));
}

// ---------------------------------------------------------------------------
// HMMA GEMM (mma.sync bf16, 3-pass split): 128x128 CTA tile, BK=64,
// 8 warps (4 M x 2 N), warp tile 32x64, fp32 register accumulators.
// SMEM tiles padded to stride 72 bf16 (conflict-free ldmatrix).
// MODE 1: A = x, C scattered into Q/K/V [B,H,T,D] (+bias)
// MODE 0: A = g_O, C = plain [M,N] (+bias)
// ---------------------------------------------------------------------------
#define TSTRIDE 72
#define TILE_B  (128*TSTRIDE*2)          // 18432 B
#define AH_OFF  0
#define AL_OFF  TILE_B
#define BH_OFF  (2*TILE_B)
#define BL_OFF  (3*TILE_B)
#define GSMEM_TOTAL (4*TILE_B)           // 73728 B

template<int MODE>
__global__ __launch_bounds__(256)
void tgemm_kernel(const float* __restrict__ A,
                  const float* __restrict__ W,
                  const float* __restrict__ bias,
                  float* __restrict__ Cout,
                  int N, int K)
{
    extern __shared__ char smc[];
    const uint32_t sb = smem_u32(smc);
    const int tid = threadIdx.x;
    const int wid = tid >> 5, lane = tid & 31;
    const int bx = blockIdx.x, by = blockIdx.y;
    const int wm = wid & 3;          // warp row (32 m each)
    const int wn = wid >> 2;         // warp col (64 n each)

    const float* Ain = (MODE == 0) ? (const float*)g_O : A;

    float acc[2][8][4];
#pragma unroll
    for (int i = 0; i < 2; i++)
#pragma unroll
        for (int j = 0; j < 8; j++)
#pragma unroll
            for (int v = 0; v < 4; v++) acc[i][j][v] = 0.f;

    // ldmatrix per-lane address components
    const int a_row = (lane & 7) + ((lane >> 3) & 1) * 8;   // 0..15
    const int a_col = (lane >> 4) * 8;                      // 0 or 8
    const int b_row = (lane & 7) + (lane >> 4) * 8;         // 0..15 (n)
    const int b_col = ((lane >> 3) & 1) * 8;                // 0 or 8 (k)

    const uint32_t aBaseRow = (uint32_t)(wm * 32 + a_row);
    const uint32_t bBaseRow = (uint32_t)(wn * 64 + b_row);

    const int NCH = K >> 6;
    for (int ch = 0; ch < NCH; ++ch) {
        const int k0 = ch << 6;

        // ---- A tile: [128 m][64 k] fp32 -> bf16 hi/lo ----
        const float* Ag = Ain + (size_t)(by * 128) * K + k0;
#pragma unroll
        for (int i = 0; i < 8; i++) {
            int idx = tid + (i << 8);
            int r = idx >> 4, c4 = (idx & 15) << 2;
            float4 a = *(const float4*)(Ag + (size_t)r * K + c4);
            uint2 hi, lo;
            split4_bf16(a, hi, lo);
            uint32_t off = (uint32_t)(r * TSTRIDE + c4) * 2;
            *(uint2*)(smc + AH_OFF + off) = hi;
            *(uint2*)(smc + AL_OFF + off) = lo;
        }

        // ---- B tile: W[k0..+64)[n0..+128) -> transposed [n][k] ----
        const float* Bg = W + (size_t)k0 * N + bx * 128;
#pragma unroll
        for (int it = 0; it < 2; ++it) {
            int blk = tid + (it << 8);      // 0..511
            int kb = blk >> 5;              // 0..15
            int nb = blk & 31;              // 0..31
            float4 w0 = *(const float4*)(Bg + (size_t)(kb * 4 + 0) * N + nb * 4);
            float4 w1 = *(const float4*)(Bg + (size_t)(kb * 4 + 1) * N + nb * 4);
            float4 w2 = *(const float4*)(Bg + (size_t)(kb * 4 + 2) * N + nb * 4);
            float4 w3 = *(const float4*)(Bg + (size_t)(kb * 4 + 3) * N + nb * 4);
            float c0[4] = {w0.x, w1.x, w2.x, w3.x};
            float c1[4] = {w0.y, w1.y, w2.y, w3.y};
            float c2[4] = {w0.z, w1.z, w2.z, w3.z};
            float c3[4] = {w0.w, w1.w, w2.w, w3.w};
            const float* cols[4] = {c0, c1, c2, c3};
#pragma unroll
            for (int dn = 0; dn < 4; ++dn) {
                float4 c = make_float4(cols[dn][0], cols[dn][1], cols[dn][2], cols[dn][3]);
                uint2 hi, lo;
                split4_bf16(c, hi, lo);
                int n = nb * 4 + dn;
                uint32_t off = (uint32_t)(n * TSTRIDE + kb * 4) * 2;
                *(uint2*)(smc + BH_OFF + off) = hi;
                *(uint2*)(smc + BL_OFF + off) = lo;
            }
        }
        __syncthreads();

        // ---- 3 split passes x 4 k16-steps ----
#pragma unroll
        for (int pass = 0; pass < 3; ++pass) {
            const uint32_t sAp = sb + ((pass == 2) ? AL_OFF : AH_OFF);
            const uint32_t sBp = sb + ((pass == 1) ? BL_OFF : BH_OFF);
#pragma unroll
            for (int kk = 0; kk < 4; ++kk) {
                const int kc = kk * 16;
                uint32_t a[2][4];
#pragma unroll
                for (int mt = 0; mt < 2; ++mt) {
                    uint32_t addr = sAp + ((aBaseRow + mt * 16) * TSTRIDE + kc + a_col) * 2;
                    ldsm_x4(a[mt][0], a[mt][1], a[mt][2], a[mt][3], addr);
                }
                uint32_t b[8][2];
#pragma unroll
                for (int np = 0; np < 4; ++np) {
                    uint32_t addr = sBp + ((bBaseRow + np * 16) * TSTRIDE + kc + b_col) * 2;
                    uint32_t r0, r1, r2, r3;
                    ldsm_x4(r0, r1, r2, r3, addr);
                    b[np*2][0] = r0; b[np*2][1] = r1;
                    b[np*2+1][0] = r2; b[np*2+1][1] = r3;
                }
#pragma unroll
                for (int mt = 0; mt < 2; ++mt)
#pragma unroll
                    for (int nt = 0; nt < 8; ++nt)
                        mma_bf16(acc[mt][nt], a[mt][0], a[mt][1], a[mt][2], a[mt][3],
                                 b[nt][0], b[nt][1]);
            }
        }
        __syncthreads();
    }

    // ---- epilogue ----
    const int tr = lane >> 2;          // 0..7
    const int tc = (lane & 3) * 2;     // 0,2,4,6
#pragma unroll
    for (int mt = 0; mt < 2; ++mt) {
#pragma unroll
        for (int nt = 0; nt < 8; ++nt) {
            const int col = bx * 128 + wn * 64 + nt * 8 + tc;
            const float b0 = __ldg(bias + col);
            const float b1 = __ldg(bias + col + 1);
#pragma unroll
            for (int h2 = 0; h2 < 2; ++h2) {
                const int m = by * 128 + wm * 32 + mt * 16 + h2 * 8 + tr;
                float2 o = make_float2(acc[mt][nt][h2*2+0] + b0,
                                       acc[mt][nt][h2*2+1] + b1);
                if (MODE == 0) {
                    *(float2*)(Cout + (size_t)m * N + col) = o;
                } else {
                    const int seg = col >> 10;
                    const int c = col & 1023;
                    const int h = c >> 6;
                    const int d = c & 63;
                    float* dst = (seg == 0) ? g_Q : (seg == 1) ? g_K : g_V;
                    const int bb = m >> 10, t = m & 1023;
                    *(float2*)(dst + (((size_t)(bb * H_ + h)) * T_ + t) * D_ + d) = o;
                }
            }
        }
    }
}

// ---------------------------------------------------------------------------
// Flash attention, fp32 SIMT (unchanged)
// ---------------------------------------------------------------------------
#define SMEM_ATTN (3*64*68*4)

__global__ __launch_bounds__(256)
void attn_kernel()
{
    extern __shared__ float sm[];
    float (*Qs)[68]  = (float (*)[68])(sm);
    float (*KPs)[68] = (float (*)[68])(sm + 64*68);
    float (*Vs)[68]  = (float (*)[68])(sm + 2*64*68);

    const int tid = threadIdx.x;
    const int tx = tid & 15, ty = tid >> 4;
    const int qt = blockIdx.x;
    const int bh = blockIdx.y;

    const float* Qg = g_Q + ((size_t)bh*T_ + qt*64)*D_;
    for (int idx = tid; idx < 64*16; idx += 256) {
        int r = idx >> 4, c4 = (idx & 15) << 2;
        *(float4*)&Qs[r][c4] = *(const float4*)(Qg + (size_t)r*D_ + c4);
    }

    float m_i[4], l_i[4], Oa[4][4];
#pragma unroll
    for (int i = 0; i < 4; i++) {
        m_i[i] = -1e30f; l_i[i] = 0.f;
#pragma unroll
        for (int j = 0; j < 4; j++) Oa[i][j] = 0.f;
    }

    for (int kt = 0; kt <= qt; ++kt) {
        const float* Kg = g_K + ((size_t)bh*T_ + kt*64)*D_;
        const float* Vg = g_V + ((size_t)bh*T_ + kt*64)*D_;

        for (int idx = tid; idx < 1024; idx += 256) {
            int c = idx & 63, d4 = (idx >> 6) << 2;
            float4 kv = *(const float4*)(Kg + (size_t)c*D_ + d4);
            KPs[d4+0][c] = kv.x; KPs[d4+1][c] = kv.y;
            KPs[d4+2][c] = kv.z; KPs[d4+3][c] = kv.w;
        }
        for (int idx = tid; idx < 1024; idx += 256) {
            int r = idx >> 4, c4 = (idx & 15) << 2;
            *(float4*)&Vs[r][c4] = *(const float4*)(Vg + (size_t)r*D_ + c4);
        }
        __syncthreads();

        float s[4][4];
#pragma unroll
        for (int i = 0; i < 4; i++)
#pragma unroll
            for (int j = 0; j < 4; j++) s[i][j] = 0.f;

#pragma unroll 4
        for (int d = 0; d < 64; d += 4) {
            float qv[4][4], kv[4][4];
#pragma unroll
            for (int i = 0; i < 4; i++) {
                float4 t = *(const float4*)&Qs[ty*4+i][d];
                qv[i][0] = t.x; qv[i][1] = t.y; qv[i][2] = t.z; qv[i][3] = t.w;
            }
#pragma unroll
            for (int k = 0; k < 4; k++) {
                float4 t = *(const float4*)&KPs[d+k][tx*4];
                kv[k][0] = t.x; kv[k][1] = t.y; kv[k][2] = t.z; kv[k][3] = t.w;
            }
#pragma unroll
            for (int i = 0; i < 4; i++)
#pragma unroll
                for (int j = 0; j < 4; j++)
                    s[i][j] += qv[i][0]*kv[0][j] + qv[i][1]*kv[1][j]
                             + qv[i][2]*kv[2][j] + qv[i][3]*kv[3][j];
        }

        const bool diag = (kt == qt);
#pragma unroll
        for (int i = 0; i < 4; i++)
#pragma unroll
            for (int j = 0; j < 4; j++) {
                float v = s[i][j] * 0.125f;
                if (diag && (tx*4 + j) > (ty*4 + i)) v = -1e30f;
                s[i][j] = v;
            }

#pragma unroll
        for (int i = 0; i < 4; i++) {
            float mx = fmaxf(fmaxf(s[i][0], s[i][1]), fmaxf(s[i][2], s[i][3]));
            mx = fmaxf(mx, __shfl_xor_sync(0xffffffffu, mx, 8));
            mx = fmaxf(mx, __shfl_xor_sync(0xffffffffu, mx, 4));
            mx = fmaxf(mx, __shfl_xor_sync(0xffffffffu, mx, 2));
            mx = fmaxf(mx, __shfl_xor_sync(0xffffffffu, mx, 1));
            float mnew  = fmaxf(m_i[i], mx);
            float alpha = __expf(m_i[i] - mnew);
            float rs = 0.f;
#pragma unroll
            for (int j = 0; j < 4; j++) { s[i][j] = __expf(s[i][j] - mnew); rs += s[i][j]; }
            rs += __shfl_xor_sync(0xffffffffu, rs, 8);
            rs += __shfl_xor_sync(0xffffffffu, rs, 4);
            rs += __shfl_xor_sync(0xffffffffu, rs, 2);
            rs += __shfl_xor_sync(0xffffffffu, rs, 1);
            l_i[i] = l_i[i]*alpha + rs;
            m_i[i] = mnew;
#pragma unroll
            for (int j = 0; j < 4; j++) Oa[i][j] *= alpha;
        }

        __syncthreads();
#pragma unroll
        for (int i = 0; i < 4; i++)
            *(float4*)&KPs[ty*4+i][tx*4] = make_float4(s[i][0], s[i][1], s[i][2], s[i][3]);
        __syncthreads();

#pragma unroll 4
        for (int c = 0; c < 64; c += 4) {
            float pv[4][4], vv[4][4];
#pragma unroll
            for (int i = 0; i < 4; i++) {
                float4 t = *(const float4*)&KPs[ty*4+i][c];
                pv[i][0] = t.x; pv[i][1] = t.y; pv[i][2] = t.z; pv[i][3] = t.w;
            }
#pragma unroll
            for (int k = 0; k < 4; k++) {
                float4 t = *(const float4*)&Vs[c+k][tx*4];
                vv[k][0] = t.x; vv[k][1] = t.y; vv[k][2] = t.z; vv[k][3] = t.w;
            }
#pragma unroll
            for (int i = 0; i < 4; i++)
#pragma unroll
                for (int j = 0; j < 4; j++)
                    Oa[i][j] += pv[i][0]*vv[0][j] + pv[i][1]*vv[1][j]
                              + pv[i][2]*vv[2][j] + pv[i][3]*vv[3][j];
        }
        __syncthreads();
    }

    const int b = bh >> 4, h = bh & 15;
#pragma unroll
    for (int i = 0; i < 4; i++) {
        float inv = 1.f / l_i[i];
        float* Op = g_O + ((size_t)(b*T_ + qt*64 + ty*4 + i))*Cc_ + h*64 + tx*4;
        *(float4*)Op = make_float4(Oa[i][0]*inv, Oa[i][1]*inv, Oa[i][2]*inv, Oa[i][3]*inv);
    }
}

// ---------------------------------------------------------------------------
extern "C" void kernel_launch(void* const* d_in, const int* in_sizes, int n_in,
                              void* d_out, int out_size)
{
    const float* x    = (const float*)d_in[0];
    const float* Wqkv = (const float*)d_in[1];
    const float* bqkv = (const float*)d_in[2];
    const float* Wout = (const float*)d_in[3];
    const float* bout = (const float*)d_in[4];
    float* out = (float*)d_out;

    cudaFuncSetAttribute(tgemm_kernel<1>,
                         cudaFuncAttributeMaxDynamicSharedMemorySize, GSMEM_TOTAL);
    cudaFuncSetAttribute(tgemm_kernel<0>,
                         cudaFuncAttributeMaxDynamicSharedMemorySize, GSMEM_TOTAL);
    cudaFuncSetAttribute(attn_kernel,
                         cudaFuncAttributeMaxDynamicSharedMemorySize, SMEM_ATTN);

    // 1) QKV projection (mma.sync bf16 3-pass split) -> Q/K/V [B,H,T,D]
    tgemm_kernel<1><<<dim3(N3_/128, M_/128), 256, GSMEM_TOTAL>>>(x, Wqkv, bqkv, nullptr, N3_, Cc_);

    // 2) causal flash attention -> g_O [B,T,C]
    attn_kernel<<<dim3(T_/64, BH_), 256, SMEM_ATTN>>>();

    // 3) output projection -> d_out
    tgemm_kernel<0><<<dim3(Cc_/128, M_/128), 256, GSMEM_TOTAL>>>(nullptr, Wout, bout, out, Cc_, Cc_);
}

// round 4
// speedup vs baseline: 1.7579x; 1.3297x over previous
#include <cuda_runtime.h>
#include <cuda_bf16.h>
#include <cstdint>

// Problem constants
#define B_   8
#define T_   1024
#define Cc_  1024
#define H_   16
#define D_   64
#define BH_  (B_*H_)     // 128
#define M_   (B_*T_)     // 8192
#define N3_  3072
#define KE_  (3*Cc_)     // 3072 (split-expanded K)

// Scratch (static device globals: allocation-free)
__device__ float g_Q[(size_t)BH_*T_*D_];
__device__ float g_K[(size_t)BH_*T_*D_];
__device__ float g_V[(size_t)BH_*T_*D_];
__device__ float g_O[(size_t)M_*Cc_];
__device__ __nv_bfloat16 g_Ac[(size_t)M_*KE_];      // A' = [hi|hi|lo], 50MB
__device__ __nv_bfloat16 g_Bqkv[(size_t)N3_*KE_];   // B'^T rows: [hi|lo|hi]
__device__ __nv_bfloat16 g_Bout[(size_t)Cc_*KE_];

// ---------------------------------------------------------------------------
__device__ __forceinline__ uint32_t smem_u32(const void* p) {
    uint32_t a;
    asm("{ .reg .u64 t; cvta.to.shared.u64 t, %1; cvt.u32.u64 %0, t; }"
        : "=r"(a) : "l"(p));
    return a;
}
__device__ __forceinline__ void ldsm_x4(uint32_t& r0, uint32_t& r1,
                                        uint32_t& r2, uint32_t& r3, uint32_t addr) {
    asm volatile("ldmatrix.sync.aligned.m8n8.x4.shared.b16 {%0,%1,%2,%3}, [%4];"
                 : "=r"(r0), "=r"(r1), "=r"(r2), "=r"(r3) : "r"(addr));
}
__device__ __forceinline__ void mma_bf16(float* d, uint32_t a0, uint32_t a1,
                                         uint32_t a2, uint32_t a3,
                                         uint32_t b0, uint32_t b1) {
    asm volatile(
        "mma.sync.aligned.m16n8k16.row.col.f32.bf16.bf16.f32 "
        "{%0,%1,%2,%3}, {%4,%5,%6,%7}, {%8,%9}, {%0,%1,%2,%3};"
        : "+f"(d[0]), "+f"(d[1]), "+f"(d[2]), "+f"(d[3])
        : "r"(a0), "r"(a1), "r"(a2), "r"(a3), "r"(b0), "r"(b1));
}
__device__ __forceinline__ void cp_async16(uint32_t saddr, const void* gaddr) {
    asm volatile("cp.async.cg.shared.global [%0], [%1], 16;"
                 :: "r"(saddr), "l"(gaddr));
}
#define CP_COMMIT() asm volatile("cp.async.commit_group;" ::: "memory")
#define CP_WAIT(n)  asm volatile("cp.async.wait_group %0;" :: "n"(n) : "memory")

__device__ __forceinline__ void split4_bf16(float4 v, uint2& hi, uint2& lo) {
    float f[4] = {v.x, v.y, v.z, v.w};
    unsigned short h[4], l[4];
#pragma unroll
    for (int i = 0; i < 4; i++) {
        __nv_bfloat16 hb = __float2bfloat16(f[i]);
        float r = f[i] - __bfloat162float(hb);
        __nv_bfloat16 lb = __float2bfloat16(r);
        h[i] = __bfloat16_as_ushort(hb);
        l[i] = __bfloat16_as_ushort(lb);
    }
    hi = make_uint2((uint32_t)h[0] | ((uint32_t)h[1] << 16),
                    (uint32_t)h[2] | ((uint32_t)h[3] << 16));
    lo = make_uint2((uint32_t)l[0] | ((uint32_t)l[1] << 16),
                    (uint32_t)l[2] | ((uint32_t)l[3] << 16));
}

// ---------------------------------------------------------------------------
// Conversion kernels (run each launch; deterministic)
// ---------------------------------------------------------------------------
// src [M][1024] fp32 -> g_Ac [M][3072] bf16 laid out [hi | hi | lo]
template<int SRC>   // 1: x (passed in), 0: g_O
__global__ __launch_bounds__(256)
void conv_act(const float* __restrict__ xin)
{
    const float* src = SRC ? xin : (const float*)g_O;
    int idx = blockIdx.x * 256 + threadIdx.x;          // over M*K/4
    int m  = idx >> 8;                                  // K/4 = 256
    int k4 = (idx & 255) << 2;
    float4 v = *(const float4*)(src + (size_t)m * Cc_ + k4);
    uint2 hi, lo;
    split4_bf16(v, hi, lo);
    __nv_bfloat16* drow = g_Ac + (size_t)m * KE_;
    *(uint2*)(drow + k4)           = hi;
    *(uint2*)(drow + Cc_ + k4)     = hi;
    *(uint2*)(drow + 2*Cc_ + k4)   = lo;
}

// W [1024][N] fp32 -> Bt [N][3072] bf16 rows laid out [hi | lo | hi]
template<int WSEL>  // 1: g_Bqkv, 0: g_Bout
__global__ __launch_bounds__(256)
void conv_w(const float* __restrict__ W, int N)
{
    __shared__ float tile[32][33];
    __nv_bfloat16* Bt = WSEL ? g_Bqkv : g_Bout;
    const int k0 = blockIdx.x * 32, n0 = blockIdx.y * 32;
    const int t = threadIdx.x;
#pragma unroll
    for (int i = 0; i < 4; i++) {
        int r = (t >> 5) + i * 8;          // k within tile
        int c = t & 31;                     // n within tile
        tile[r][c] = W[(size_t)(k0 + r) * N + n0 + c];
    }
    __syncthreads();
#pragma unroll
    for (int i = 0; i < 4; i++) {
        int nr = (t >> 5) + i * 8;
        int kc = t & 31;
        float v = tile[kc][nr];
        __nv_bfloat16 hb = __float2bfloat16(v);
        float res = v - __bfloat162float(hb);
        __nv_bfloat16 lb = __float2bfloat16(res);
        __nv_bfloat16* row = Bt + (size_t)(n0 + nr) * KE_;
        row[k0 + kc]           = hb;
        row[Cc_ + k0 + kc]     = lb;
        row[2*Cc_ + k0 + kc]   = hb;
    }
}

// ---------------------------------------------------------------------------
// Pipelined bf16 HMMA GEMM: 128x128 CTA tile, BK=64, K_eff=3072 (48 chunks),
// 3-stage cp.async pipeline, 8 warps (4M x 2N), warp tile 32x64.
// MODE 1: C scattered into Q/K/V [B,H,T,D] (+bias), B = g_Bqkv, N=3072
// MODE 0: C = plain [M,N] (+bias), B = g_Bout, N=1024
// ---------------------------------------------------------------------------
#define TSTRIDE 72
#define TILE_B  (128*TSTRIDE*2)          // 18432 B
#define STAGE_B (2*TILE_B)               // A + B per stage
#define NSTAGE  3
#define GSMEM_TOTAL (NSTAGE*STAGE_B)     // 110592 B
#define NCH     (KE_/64)                 // 48

template<int MODE>
__global__ __launch_bounds__(256)
void tgemm_kernel(const float* __restrict__ bias,
                  float* __restrict__ Cout,
                  int N)
{
    extern __shared__ char smc[];
    const uint32_t sb = smem_u32(smc);
    const int tid = threadIdx.x;
    const int wid = tid >> 5, lane = tid & 31;
    const int bx = blockIdx.x, by = blockIdx.y;
    const int wm = wid & 3;
    const int wn = wid >> 2;

    const __nv_bfloat16* Abf = g_Ac + (size_t)(by * 128) * KE_;
    const __nv_bfloat16* Bbf = (MODE ? g_Bqkv : g_Bout) + (size_t)(bx * 128) * KE_;

    // per-thread cp.async pattern: 8 chunks/row of 16B; t>>3 = row base, t&7 = chunk
    const int lrow = tid >> 3;          // 0..31
    const int lch  = tid & 7;           // 0..7
    const uint32_t sAoff = (uint32_t)(lrow * TSTRIDE * 2 + lch * 16);

    float acc[2][8][4];
#pragma unroll
    for (int i = 0; i < 2; i++)
#pragma unroll
        for (int j = 0; j < 8; j++)
#pragma unroll
            for (int v = 0; v < 4; v++) acc[i][j][v] = 0.f;

    const int a_row = (lane & 7) + ((lane >> 3) & 1) * 8;
    const int a_col = (lane >> 4) * 8;
    const int b_row = (lane & 7) + (lane >> 4) * 8;
    const int b_col = ((lane >> 3) & 1) * 8;
    const uint32_t aBaseRow = (uint32_t)(wm * 32 + a_row);
    const uint32_t bBaseRow = (uint32_t)(wn * 64 + b_row);

    // -------- pipeline --------
    auto load_stage = [&](int st, int ch) {
        const uint32_t sA = sb + st * STAGE_B + sAoff;
        const uint32_t sB = sA + TILE_B;
        const __nv_bfloat16* Ag = Abf + (size_t)lrow * KE_ + ch * 64 + lch * 8;
        const __nv_bfloat16* Bg = Bbf + (size_t)lrow * KE_ + ch * 64 + lch * 8;
#pragma unroll
        for (int i = 0; i < 4; i++) {
            cp_async16(sA + i * 32 * TSTRIDE * 2, Ag + (size_t)(i * 32) * KE_);
            cp_async16(sB + i * 32 * TSTRIDE * 2, Bg + (size_t)(i * 32) * KE_);
        }
    };

#pragma unroll
    for (int s = 0; s < NSTAGE - 1; ++s) {
        load_stage(s, s);
        CP_COMMIT();
    }

    for (int ch = 0; ch < NCH; ++ch) {
        const int lc = ch + NSTAGE - 1;
        if (lc < NCH) load_stage(lc % NSTAGE, lc);
        CP_COMMIT();
        CP_WAIT(NSTAGE - 1);           // stage ch resident
        __syncthreads();

        const uint32_t sAp = sb + (ch % NSTAGE) * STAGE_B;
        const uint32_t sBp = sAp + TILE_B;
#pragma unroll
        for (int kk = 0; kk < 4; ++kk) {
            const int kc = kk * 16;
            uint32_t a[2][4];
#pragma unroll
            for (int mt = 0; mt < 2; ++mt) {
                uint32_t addr = sAp + ((aBaseRow + mt * 16) * TSTRIDE + kc + a_col) * 2;
                ldsm_x4(a[mt][0], a[mt][1], a[mt][2], a[mt][3], addr);
            }
            uint32_t b[8][2];
#pragma unroll
            for (int np = 0; np < 4; ++np) {
                uint32_t addr = sBp + ((bBaseRow + np * 16) * TSTRIDE + kc + b_col) * 2;
                uint32_t r0, r1, r2, r3;
                ldsm_x4(r0, r1, r2, r3, addr);
                b[np*2][0] = r0; b[np*2][1] = r1;
                b[np*2+1][0] = r2; b[np*2+1][1] = r3;
            }
#pragma unroll
            for (int mt = 0; mt < 2; ++mt)
#pragma unroll
                for (int nt = 0; nt < 8; ++nt)
                    mma_bf16(acc[mt][nt], a[mt][0], a[mt][1], a[mt][2], a[mt][3],
                             b[nt][0], b[nt][1]);
        }
        __syncthreads();
    }

    // -------- epilogue --------
    const int tr = lane >> 2;
    const int tc = (lane & 3) * 2;
#pragma unroll
    for (int mt = 0; mt < 2; ++mt) {
#pragma unroll
        for (int nt = 0; nt < 8; ++nt) {
            const int col = bx * 128 + wn * 64 + nt * 8 + tc;
            const float b0 = __ldg(bias + col);
            const float b1 = __ldg(bias + col + 1);
#pragma unroll
            for (int h2 = 0; h2 < 2; ++h2) {
                const int m = by * 128 + wm * 32 + mt * 16 + h2 * 8 + tr;
                float2 o = make_float2(acc[mt][nt][h2*2+0] + b0,
                                       acc[mt][nt][h2*2+1] + b1);
                if (MODE == 0) {
                    *(float2*)(Cout + (size_t)m * N + col) = o;
                } else {
                    const int seg = col >> 10;
                    const int c = col & 1023;
                    const int h = c >> 6;
                    const int d = c & 63;
                    float* dst = (seg == 0) ? g_Q : (seg == 1) ? g_K : g_V;
                    const int bb = m >> 10, t = m & 1023;
                    *(float2*)(dst + (((size_t)(bb * H_ + h)) * T_ + t) * D_ + d) = o;
                }
            }
        }
    }
}

// ---------------------------------------------------------------------------
// Flash attention, fp32 SIMT (unchanged)
// ---------------------------------------------------------------------------
#define SMEM_ATTN (3*64*68*4)

__global__ __launch_bounds__(256)
void attn_kernel()
{
    extern __shared__ float sm[];
    float (*Qs)[68]  = (float (*)[68])(sm);
    float (*KPs)[68] = (float (*)[68])(sm + 64*68);
    float (*Vs)[68]  = (float (*)[68])(sm + 2*64*68);

    const int tid = threadIdx.x;
    const int tx = tid & 15, ty = tid >> 4;
    const int qt = blockIdx.x;
    const int bh = blockIdx.y;

    const float* Qg = g_Q + ((size_t)bh*T_ + qt*64)*D_;
    for (int idx = tid; idx < 64*16; idx += 256) {
        int r = idx >> 4, c4 = (idx & 15) << 2;
        *(float4*)&Qs[r][c4] = *(const float4*)(Qg + (size_t)r*D_ + c4);
    }

    float m_i[4], l_i[4], Oa[4][4];
#pragma unroll
    for (int i = 0; i < 4; i++) {
        m_i[i] = -1e30f; l_i[i] = 0.f;
#pragma unroll
        for (int j = 0; j < 4; j++) Oa[i][j] = 0.f;
    }

    for (int kt = 0; kt <= qt; ++kt) {
        const float* Kg = g_K + ((size_t)bh*T_ + kt*64)*D_;
        const float* Vg = g_V + ((size_t)bh*T_ + kt*64)*D_;

        for (int idx = tid; idx < 1024; idx += 256) {
            int c = idx & 63, d4 = (idx >> 6) << 2;
            float4 kv = *(const float4*)(Kg + (size_t)c*D_ + d4);
            KPs[d4+0][c] = kv.x; KPs[d4+1][c] = kv.y;
            KPs[d4+2][c] = kv.z; KPs[d4+3][c] = kv.w;
        }
        for (int idx = tid; idx < 1024; idx += 256) {
            int r = idx >> 4, c4 = (idx & 15) << 2;
            *(float4*)&Vs[r][c4] = *(const float4*)(Vg + (size_t)r*D_ + c4);
        }
        __syncthreads();

        float s[4][4];
#pragma unroll
        for (int i = 0; i < 4; i++)
#pragma unroll
            for (int j = 0; j < 4; j++) s[i][j] = 0.f;

#pragma unroll 4
        for (int d = 0; d < 64; d += 4) {
            float qv[4][4], kv[4][4];
#pragma unroll
            for (int i = 0; i < 4; i++) {
                float4 t = *(const float4*)&Qs[ty*4+i][d];
                qv[i][0] = t.x; qv[i][1] = t.y; qv[i][2] = t.z; qv[i][3] = t.w;
            }
#pragma unroll
            for (int k = 0; k < 4; k++) {
                float4 t = *(const float4*)&KPs[d+k][tx*4];
                kv[k][0] = t.x; kv[k][1] = t.y; kv[k][2] = t.z; kv[k][3] = t.w;
            }
#pragma unroll
            for (int i = 0; i < 4; i++)
#pragma unroll
                for (int j = 0; j < 4; j++)
                    s[i][j] += qv[i][0]*kv[0][j] + qv[i][1]*kv[1][j]
                             + qv[i][2]*kv[2][j] + qv[i][3]*kv[3][j];
        }

        const bool diag = (kt == qt);
#pragma unroll
        for (int i = 0; i < 4; i++)
#pragma unroll
            for (int j = 0; j < 4; j++) {
                float v = s[i][j] * 0.125f;
                if (diag && (tx*4 + j) > (ty*4 + i)) v = -1e30f;
                s[i][j] = v;
            }

#pragma unroll
        for (int i = 0; i < 4; i++) {
            float mx = fmaxf(fmaxf(s[i][0], s[i][1]), fmaxf(s[i][2], s[i][3]));
            mx = fmaxf(mx, __shfl_xor_sync(0xffffffffu, mx, 8));
            mx = fmaxf(mx, __shfl_xor_sync(0xffffffffu, mx, 4));
            mx = fmaxf(mx, __shfl_xor_sync(0xffffffffu, mx, 2));
            mx = fmaxf(mx, __shfl_xor_sync(0xffffffffu, mx, 1));
            float mnew  = fmaxf(m_i[i], mx);
            float alpha = __expf(m_i[i] - mnew);
            float rs = 0.f;
#pragma unroll
            for (int j = 0; j < 4; j++) { s[i][j] = __expf(s[i][j] - mnew); rs += s[i][j]; }
            rs += __shfl_xor_sync(0xffffffffu, rs, 8);
            rs += __shfl_xor_sync(0xffffffffu, rs, 4);
            rs += __shfl_xor_sync(0xffffffffu, rs, 2);
            rs += __shfl_xor_sync(0xffffffffu, rs, 1);
            l_i[i] = l_i[i]*alpha + rs;
            m_i[i] = mnew;
#pragma unroll
            for (int j = 0; j < 4; j++) Oa[i][j] *= alpha;
        }

        __syncthreads();
#pragma unroll
        for (int i = 0; i < 4; i++)
            *(float4*)&KPs[ty*4+i][tx*4] = make_float4(s[i][0], s[i][1], s[i][2], s[i][3]);
        __syncthreads();

#pragma unroll 4
        for (int c = 0; c < 64; c += 4) {
            float pv[4][4], vv[4][4];
#pragma unroll
            for (int i = 0; i < 4; i++) {
                float4 t = *(const float4*)&KPs[ty*4+i][c];
                pv[i][0] = t.x; pv[i][1] = t.y; pv[i][2] = t.z; pv[i][3] = t.w;
            }
#pragma unroll
            for (int k = 0; k < 4; k++) {
                float4 t = *(const float4*)&Vs[c+k][tx*4];
                vv[k][0] = t.x; vv[k][1] = t.y; vv[k][2] = t.z; vv[k][3] = t.w;
            }
#pragma unroll
            for (int i = 0; i < 4; i++)
#pragma unroll
                for (int j = 0; j < 4; j++)
                    Oa[i][j] += pv[i][0]*vv[0][j] + pv[i][1]*vv[1][j]
                              + pv[i][2]*vv[2][j] + pv[i][3]*vv[3][j];
        }
        __syncthreads();
    }

    const int b = bh >> 4, h = bh & 15;
#pragma unroll
    for (int i = 0; i < 4; i++) {
        float inv = 1.f / l_i[i];
        float* Op = g_O + ((size_t)(b*T_ + qt*64 + ty*4 + i))*Cc_ + h*64 + tx*4;
        *(float4*)Op = make_float4(Oa[i][0]*inv, Oa[i][1]*inv, Oa[i][2]*inv, Oa[i][3]*inv);
    }
}

// ---------------------------------------------------------------------------
extern "C" void kernel_launch(void* const* d_in, const int* in_sizes, int n_in,
                              void* d_out, int out_size)
{
    const float* x    = (const float*)d_in[0];
    const float* Wqkv = (const float*)d_in[1];
    const float* bqkv = (const float*)d_in[2];
    const float* Wout = (const float*)d_in[3];
    const float* bout = (const float*)d_in[4];
    float* out = (float*)d_out;

    cudaFuncSetAttribute(tgemm_kernel<1>,
                         cudaFuncAttributeMaxDynamicSharedMemorySize, GSMEM_TOTAL);
    cudaFuncSetAttribute(tgemm_kernel<0>,
                         cudaFuncAttributeMaxDynamicSharedMemorySize, GSMEM_TOTAL);
    cudaFuncSetAttribute(attn_kernel,
                         cudaFuncAttributeMaxDynamicSharedMemorySize, SMEM_ATTN);

    // 0) split conversions
    conv_w<1><<<dim3(Cc_/32, N3_/32), 256>>>(Wqkv, N3_);
    conv_w<0><<<dim3(Cc_/32, Cc_/32), 256>>>(Wout, Cc_);
    conv_act<1><<<M_*Cc_/4/256, 256>>>(x);

    // 1) QKV projection -> Q/K/V [B,H,T,D]
    tgemm_kernel<1><<<dim3(N3_/128, M_/128), 256, GSMEM_TOTAL>>>(bqkv, nullptr, N3_);

    // 2) causal flash attention -> g_O [B,T,C]
    attn_kernel<<<dim3(T_/64, BH_), 256, SMEM_ATTN>>>();

    // 3) convert attention output, then output projection -> d_out
    conv_act<0><<<M_*Cc_/4/256, 256>>>(nullptr);
    tgemm_kernel<0><<<dim3(Cc_/128, M_/128), 256, GSMEM_TOTAL>>>(bout, out, Cc_);
}

// round 5
// speedup vs baseline: 2.5275x; 1.4378x over previous
#include <cuda_runtime.h>
#include <cuda_bf16.h>
#include <cstdint>

// Problem constants
#define B_   8
#define T_   1024
#define Cc_  1024
#define H_   16
#define D_   64
#define BH_  (B_*H_)     // 128
#define M_   (B_*T_)     // 8192
#define N3_  3072
#define KE_  (3*Cc_)     // 3072 (split-expanded K)

// Scratch (static device globals: allocation-free)
__device__ __nv_bfloat16 g_Qh[(size_t)BH_*T_*D_], g_Ql[(size_t)BH_*T_*D_];
__device__ __nv_bfloat16 g_Kh[(size_t)BH_*T_*D_], g_Kl[(size_t)BH_*T_*D_];
__device__ __nv_bfloat16 g_Vh[(size_t)BH_*T_*D_], g_Vl[(size_t)BH_*T_*D_];
__device__ __nv_bfloat16 g_Ac[(size_t)M_*KE_];      // A' = [hi|hi|lo]
__device__ __nv_bfloat16 g_Bqkv[(size_t)N3_*KE_];   // B'^T rows: [hi|lo|hi]
__device__ __nv_bfloat16 g_Bout[(size_t)Cc_*KE_];

// ---------------------------------------------------------------------------
__device__ __forceinline__ uint32_t smem_u32(const void* p) {
    uint32_t a;
    asm("{ .reg .u64 t; cvta.to.shared.u64 t, %1; cvt.u32.u64 %0, t; }"
        : "=r"(a) : "l"(p));
    return a;
}
__device__ __forceinline__ void ldsm_x4(uint32_t& r0, uint32_t& r1,
                                        uint32_t& r2, uint32_t& r3, uint32_t addr) {
    asm volatile("ldmatrix.sync.aligned.m8n8.x4.shared.b16 {%0,%1,%2,%3}, [%4];"
                 : "=r"(r0), "=r"(r1), "=r"(r2), "=r"(r3) : "r"(addr));
}
__device__ __forceinline__ void ldsm_x4_t(uint32_t& r0, uint32_t& r1,
                                          uint32_t& r2, uint32_t& r3, uint32_t addr) {
    asm volatile("ldmatrix.sync.aligned.m8n8.x4.trans.shared.b16 {%0,%1,%2,%3}, [%4];"
                 : "=r"(r0), "=r"(r1), "=r"(r2), "=r"(r3) : "r"(addr));
}
__device__ __forceinline__ void mma_bf16(float* d, uint32_t a0, uint32_t a1,
                                         uint32_t a2, uint32_t a3,
                                         uint32_t b0, uint32_t b1) {
    asm volatile(
        "mma.sync.aligned.m16n8k16.row.col.f32.bf16.bf16.f32 "
        "{%0,%1,%2,%3}, {%4,%5,%6,%7}, {%8,%9}, {%0,%1,%2,%3};"
        : "+f"(d[0]), "+f"(d[1]), "+f"(d[2]), "+f"(d[3])
        : "r"(a0), "r"(a1), "r"(a2), "r"(a3), "r"(b0), "r"(b1));
}
__device__ __forceinline__ void cp_async16(uint32_t saddr, const void* gaddr) {
    asm volatile("cp.async.cg.shared.global [%0], [%1], 16;"
                 :: "r"(saddr), "l"(gaddr));
}
#define CP_COMMIT() asm volatile("cp.async.commit_group;" ::: "memory")
#define CP_WAIT(n)  asm volatile("cp.async.wait_group %0;" :: "n"(n) : "memory")

__device__ __forceinline__ void split4_bf16(float4 v, uint2& hi, uint2& lo) {
    float f[4] = {v.x, v.y, v.z, v.w};
    unsigned short h[4], l[4];
#pragma unroll
    for (int i = 0; i < 4; i++) {
        __nv_bfloat16 hb = __float2bfloat16(f[i]);
        float r = f[i] - __bfloat162float(hb);
        __nv_bfloat16 lb = __float2bfloat16(r);
        h[i] = __bfloat16_as_ushort(hb);
        l[i] = __bfloat16_as_ushort(lb);
    }
    hi = make_uint2((uint32_t)h[0] | ((uint32_t)h[1] << 16),
                    (uint32_t)h[2] | ((uint32_t)h[3] << 16));
    lo = make_uint2((uint32_t)l[0] | ((uint32_t)l[1] << 16),
                    (uint32_t)l[2] | ((uint32_t)l[3] << 16));
}
__device__ __forceinline__ void split2_pack(float x, float y, uint32_t& hi, uint32_t& lo) {
    __nv_bfloat16 hx = __float2bfloat16(x), hy = __float2bfloat16(y);
    __nv_bfloat16 lx = __float2bfloat16(x - __bfloat162float(hx));
    __nv_bfloat16 ly = __float2bfloat16(y - __bfloat162float(hy));
    hi = (uint32_t)__bfloat16_as_ushort(hx) | ((uint32_t)__bfloat16_as_ushort(hy) << 16);
    lo = (uint32_t)__bfloat16_as_ushort(lx) | ((uint32_t)__bfloat16_as_ushort(ly) << 16);
}

// ---------------------------------------------------------------------------
// Conversion kernels
// ---------------------------------------------------------------------------
// x [M][1024] fp32 -> g_Ac [M][3072] bf16 [hi | hi | lo]
__global__ __launch_bounds__(256)
void conv_act(const float* __restrict__ src)
{
    int idx = blockIdx.x * 256 + threadIdx.x;
    int m  = idx >> 8;
    int k4 = (idx & 255) << 2;
    float4 v = *(const float4*)(src + (size_t)m * Cc_ + k4);
    uint2 hi, lo;
    split4_bf16(v, hi, lo);
    __nv_bfloat16* drow = g_Ac + (size_t)m * KE_;
    *(uint2*)(drow + k4)         = hi;
    *(uint2*)(drow + Cc_ + k4)   = hi;
    *(uint2*)(drow + 2*Cc_ + k4) = lo;
}

// W [1024][N] fp32 -> Bt [N][3072] bf16 rows [hi | lo | hi]
template<int WSEL>  // 1: g_Bqkv, 0: g_Bout
__global__ __launch_bounds__(256)
void conv_w(const float* __restrict__ W, int N)
{
    __shared__ float tile[32][33];
    __nv_bfloat16* Bt = WSEL ? g_Bqkv : g_Bout;
    const int k0 = blockIdx.x * 32, n0 = blockIdx.y * 32;
    const int t = threadIdx.x;
#pragma unroll
    for (int i = 0; i < 4; i++) {
        int r = (t >> 5) + i * 8;
        int c = t & 31;
        tile[r][c] = W[(size_t)(k0 + r) * N + n0 + c];
    }
    __syncthreads();
#pragma unroll
    for (int i = 0; i < 4; i++) {
        int nr = (t >> 5) + i * 8;
        int kc = t & 31;
        float v = tile[kc][nr];
        __nv_bfloat16 hb = __float2bfloat16(v);
        float res = v - __bfloat162float(hb);
        __nv_bfloat16 lb = __float2bfloat16(res);
        __nv_bfloat16* row = Bt + (size_t)(n0 + nr) * KE_;
        row[k0 + kc]         = hb;
        row[Cc_ + k0 + kc]   = lb;
        row[2*Cc_ + k0 + kc] = hb;
    }
}

// ---------------------------------------------------------------------------
// Pipelined bf16 HMMA GEMM (as R4). MODE 1: epilogue -> split Q/K/V bf16 hi/lo.
// MODE 0: plain fp32 out.
// ---------------------------------------------------------------------------
#define TSTRIDE 72
#define TILE_B  (128*TSTRIDE*2)
#define STAGE_B (2*TILE_B)
#define NSTAGE  3
#define GSMEM_TOTAL (NSTAGE*STAGE_B)
#define NCH     (KE_/64)

template<int MODE>
__global__ __launch_bounds__(256)
void tgemm_kernel(const float* __restrict__ bias,
                  float* __restrict__ Cout,
                  int N)
{
    extern __shared__ char smc[];
    const uint32_t sb = smem_u32(smc);
    const int tid = threadIdx.x;
    const int wid = tid >> 5, lane = tid & 31;
    const int bx = blockIdx.x, by = blockIdx.y;
    const int wm = wid & 3;
    const int wn = wid >> 2;

    const __nv_bfloat16* Abf = g_Ac + (size_t)(by * 128) * KE_;
    const __nv_bfloat16* Bbf = (MODE ? g_Bqkv : g_Bout) + (size_t)(bx * 128) * KE_;

    const int lrow = tid >> 3;
    const int lch  = tid & 7;
    const uint32_t sAoff = (uint32_t)(lrow * TSTRIDE * 2 + lch * 16);

    float acc[2][8][4];
#pragma unroll
    for (int i = 0; i < 2; i++)
#pragma unroll
        for (int j = 0; j < 8; j++)
#pragma unroll
            for (int v = 0; v < 4; v++) acc[i][j][v] = 0.f;

    const int a_row = (lane & 7) + ((lane >> 3) & 1) * 8;
    const int a_col = (lane >> 4) * 8;
    const int b_row = (lane & 7) + (lane >> 4) * 8;
    const int b_col = ((lane >> 3) & 1) * 8;
    const uint32_t aBaseRow = (uint32_t)(wm * 32 + a_row);
    const uint32_t bBaseRow = (uint32_t)(wn * 64 + b_row);

    auto load_stage = [&](int st, int ch) {
        const uint32_t sA = sb + st * STAGE_B + sAoff;
        const uint32_t sB = sA + TILE_B;
        const __nv_bfloat16* Ag = Abf + (size_t)lrow * KE_ + ch * 64 + lch * 8;
        const __nv_bfloat16* Bg = Bbf + (size_t)lrow * KE_ + ch * 64 + lch * 8;
#pragma unroll
        for (int i = 0; i < 4; i++) {
            cp_async16(sA + i * 32 * TSTRIDE * 2, Ag + (size_t)(i * 32) * KE_);
            cp_async16(sB + i * 32 * TSTRIDE * 2, Bg + (size_t)(i * 32) * KE_);
        }
    };

#pragma unroll
    for (int s = 0; s < NSTAGE - 1; ++s) {
        load_stage(s, s);
        CP_COMMIT();
    }

    for (int ch = 0; ch < NCH; ++ch) {
        const int lc = ch + NSTAGE - 1;
        if (lc < NCH) load_stage(lc % NSTAGE, lc);
        CP_COMMIT();
        CP_WAIT(NSTAGE - 1);
        __syncthreads();

        const uint32_t sAp = sb + (ch % NSTAGE) * STAGE_B;
        const uint32_t sBp = sAp + TILE_B;
#pragma unroll
        for (int kk = 0; kk < 4; ++kk) {
            const int kc = kk * 16;
            uint32_t a[2][4];
#pragma unroll
            for (int mt = 0; mt < 2; ++mt) {
                uint32_t addr = sAp + ((aBaseRow + mt * 16) * TSTRIDE + kc + a_col) * 2;
                ldsm_x4(a[mt][0], a[mt][1], a[mt][2], a[mt][3], addr);
            }
            uint32_t b[8][2];
#pragma unroll
            for (int np = 0; np < 4; ++np) {
                uint32_t addr = sBp + ((bBaseRow + np * 16) * TSTRIDE + kc + b_col) * 2;
                uint32_t r0, r1, r2, r3;
                ldsm_x4(r0, r1, r2, r3, addr);
                b[np*2][0] = r0; b[np*2][1] = r1;
                b[np*2+1][0] = r2; b[np*2+1][1] = r3;
            }
#pragma unroll
            for (int mt = 0; mt < 2; ++mt)
#pragma unroll
                for (int nt = 0; nt < 8; ++nt)
                    mma_bf16(acc[mt][nt], a[mt][0], a[mt][1], a[mt][2], a[mt][3],
                             b[nt][0], b[nt][1]);
        }
        __syncthreads();
    }

    // -------- epilogue --------
    const int tr = lane >> 2;
    const int tc = (lane & 3) * 2;
#pragma unroll
    for (int mt = 0; mt < 2; ++mt) {
#pragma unroll
        for (int nt = 0; nt < 8; ++nt) {
            const int col = bx * 128 + wn * 64 + nt * 8 + tc;
            const float b0 = __ldg(bias + col);
            const float b1 = __ldg(bias + col + 1);
#pragma unroll
            for (int h2 = 0; h2 < 2; ++h2) {
                const int m = by * 128 + wm * 32 + mt * 16 + h2 * 8 + tr;
                float ox = acc[mt][nt][h2*2+0] + b0;
                float oy = acc[mt][nt][h2*2+1] + b1;
                if (MODE == 0) {
                    *(float2*)(Cout + (size_t)m * N + col) = make_float2(ox, oy);
                } else {
                    const int seg = col >> 10;
                    const int c = col & 1023;
                    const int h = c >> 6;
                    const int d = c & 63;
                    const int bb = m >> 10, t = m & 1023;
                    if (seg == 0) { ox *= 0.125f; oy *= 0.125f; }  // fold 1/sqrt(D)
                    uint32_t hw, lw;
                    split2_pack(ox, oy, hw, lw);
                    size_t idx = (((size_t)(bb * H_ + h)) * T_ + t) * D_ + d;
                    __nv_bfloat16 *dh, *dl;
                    if (seg == 0)      { dh = g_Qh; dl = g_Ql; }
                    else if (seg == 1) { dh = g_Kh; dl = g_Kl; }
                    else               { dh = g_Vh; dl = g_Vl; }
                    *(uint32_t*)(dh + idx) = hw;
                    *(uint32_t*)(dl + idx) = lw;
                }
            }
        }
    }
}

// ---------------------------------------------------------------------------
// HMMA flash attention: CTA = 128 q-rows x one (b,h). 8 warps, 16 rows each,
// full 64-key/64-d warp tile. Q frags register-resident; K/V hi/lo double-
// buffered cp.async. 3-pass split for S and PV. Epilogue -> g_Ac [hi|hi|lo].
// ---------------------------------------------------------------------------
#define AST 72
#define QH_OFF 0
#define QL_OFF (128*AST*2)
#define STG0   (2*128*AST*2)
#define KTILE_B (64*AST*2)
#define STG_B  (4*KTILE_B)
#define ASMEM_TOTAL (STG0 + 2*STG_B)   // 110592

__global__ __launch_bounds__(256)
void attn_kernel()
{
    extern __shared__ char smc[];
    const uint32_t sb = smem_u32(smc);
    const int tid = threadIdx.x, wid = tid >> 5, lane = tid & 31;
    const int qt = blockIdx.x, bh = blockIdx.y;
    const int q0 = qt * 128;
    const size_t base = (size_t)bh * T_ * D_;

    // Q hi/lo -> smem (group 0)
    {
        const __nv_bfloat16* Qh = g_Qh + base + (size_t)q0 * D_;
        const __nv_bfloat16* Ql = g_Ql + base + (size_t)q0 * D_;
#pragma unroll
        for (int i = 0; i < 4; i++) {
            int idx = tid + i * 256;
            int r = idx >> 3, c = idx & 7;
            cp_async16(sb + QH_OFF + (uint32_t)(r * AST + c * 8) * 2, Qh + (size_t)r * 64 + c * 8);
            cp_async16(sb + QL_OFF + (uint32_t)(r * AST + c * 8) * 2, Ql + (size_t)r * 64 + c * 8);
        }
        CP_COMMIT();
    }

    const int KT = 2 * qt + 2;

    auto load_stage = [&](int st, int kt) {
        const uint32_t s0 = sb + STG0 + st * STG_B;
        const __nv_bfloat16* srcs[4] = {
            g_Kh + base + (size_t)kt * 64 * D_,
            g_Kl + base + (size_t)kt * 64 * D_,
            g_Vh + base + (size_t)kt * 64 * D_,
            g_Vl + base + (size_t)kt * 64 * D_ };
#pragma unroll
        for (int tg = 0; tg < 4; tg++) {
#pragma unroll
            for (int it = 0; it < 2; it++) {
                int r = (tid >> 3) + it * 32, c = tid & 7;
                cp_async16(s0 + tg * KTILE_B + (uint32_t)(r * AST + c * 8) * 2,
                           srcs[tg] + (size_t)r * 64 + c * 8);
            }
        }
    };

    load_stage(0, 0); CP_COMMIT();

    const int a_row = (lane & 7) + ((lane >> 3) & 1) * 8;
    const int a_col = (lane >> 4) * 8;
    const int b_row = (lane & 7) + (lane >> 4) * 8;
    const int b_col = ((lane >> 3) & 1) * 8;
    const int v_row = lane & 15;
    const int v_col = (lane >> 4) * 8;
    const int wm = wid;                    // 16 rows per warp

    uint32_t qh[4][4], ql[4][4];
    float m_[2] = {-1e30f, -1e30f}, l_[2] = {0.f, 0.f};
    float oacc[8][4];
#pragma unroll
    for (int i = 0; i < 8; i++)
#pragma unroll
        for (int v = 0; v < 4; v++) oacc[i][v] = 0.f;

    const int rbase = q0 + wm * 16;

    for (int kt = 0; kt < KT; ++kt) {
        if (kt + 1 < KT) { load_stage((kt + 1) & 1, kt + 1); CP_COMMIT(); CP_WAIT(1); }
        else             { CP_WAIT(0); }
        __syncthreads();

        if (kt == 0) {
#pragma unroll
            for (int ks = 0; ks < 4; ks++) {
                uint32_t aq = sb + QH_OFF + (uint32_t)((wm * 16 + a_row) * AST + ks * 16 + a_col) * 2;
                ldsm_x4(qh[ks][0], qh[ks][1], qh[ks][2], qh[ks][3], aq);
                ldsm_x4(ql[ks][0], ql[ks][1], ql[ks][2], ql[ks][3], aq + (QL_OFF - QH_OFF));
            }
        }

        const bool active = (kt * 64) <= (rbase + 15);
        if (active) {
            const uint32_t sKh = sb + STG0 + (kt & 1) * STG_B;
            const uint32_t sKl = sKh + KTILE_B;
            const uint32_t sVh = sKh + 2 * KTILE_B;
            const uint32_t sVl = sKh + 3 * KTILE_B;

            // ---- S = Qhi*Khi + Qlo*Khi + Qhi*Klo ----
            float sacc[8][4];
#pragma unroll
            for (int i = 0; i < 8; i++)
#pragma unroll
                for (int v = 0; v < 4; v++) sacc[i][v] = 0.f;

#pragma unroll
            for (int ks = 0; ks < 4; ks++) {
                uint32_t kf[4][4];
#pragma unroll
                for (int np = 0; np < 4; np++) {
                    uint32_t addr = sKh + (uint32_t)((np * 16 + b_row) * AST + ks * 16 + b_col) * 2;
                    ldsm_x4(kf[np][0], kf[np][1], kf[np][2], kf[np][3], addr);
                }
#pragma unroll
                for (int np = 0; np < 4; np++) {
                    mma_bf16(sacc[2*np],   qh[ks][0], qh[ks][1], qh[ks][2], qh[ks][3], kf[np][0], kf[np][1]);
                    mma_bf16(sacc[2*np+1], qh[ks][0], qh[ks][1], qh[ks][2], qh[ks][3], kf[np][2], kf[np][3]);
                    mma_bf16(sacc[2*np],   ql[ks][0], ql[ks][1], ql[ks][2], ql[ks][3], kf[np][0], kf[np][1]);
                    mma_bf16(sacc[2*np+1], ql[ks][0], ql[ks][1], ql[ks][2], ql[ks][3], kf[np][2], kf[np][3]);
                }
#pragma unroll
                for (int np = 0; np < 4; np++) {
                    uint32_t addr = sKl + (uint32_t)((np * 16 + b_row) * AST + ks * 16 + b_col) * 2;
                    ldsm_x4(kf[np][0], kf[np][1], kf[np][2], kf[np][3], addr);
                }
#pragma unroll
                for (int np = 0; np < 4; np++) {
                    mma_bf16(sacc[2*np],   qh[ks][0], qh[ks][1], qh[ks][2], qh[ks][3], kf[np][0], kf[np][1]);
                    mma_bf16(sacc[2*np+1], qh[ks][0], qh[ks][1], qh[ks][2], qh[ks][3], kf[np][2], kf[np][3]);
                }
            }

            // ---- causal mask (warp tile touches diagonal?) ----
            if (kt * 64 + 63 > rbase) {
                const int r0r = rbase + (lane >> 2);
#pragma unroll
                for (int nt = 0; nt < 8; nt++) {
#pragma unroll
                    for (int v = 0; v < 4; v++) {
                        int col = kt * 64 + nt * 8 + 2 * (lane & 3) + (v & 1);
                        int row = r0r + (v >> 1) * 8;
                        if (col > row) sacc[nt][v] = -1e30f;
                    }
                }
            }

            // ---- online softmax (rows warp-local; 4 lanes/row) ----
            float alpha[2];
#pragma unroll
            for (int h2 = 0; h2 < 2; h2++) {
                float mx = -1e30f;
#pragma unroll
                for (int nt = 0; nt < 8; nt++)
                    mx = fmaxf(mx, fmaxf(sacc[nt][2*h2], sacc[nt][2*h2+1]));
                mx = fmaxf(mx, __shfl_xor_sync(0xffffffffu, mx, 1));
                mx = fmaxf(mx, __shfl_xor_sync(0xffffffffu, mx, 2));
                float mnew = fmaxf(m_[h2], mx);
                alpha[h2] = __expf(m_[h2] - mnew);
                float rs = 0.f;
#pragma unroll
                for (int nt = 0; nt < 8; nt++) {
                    sacc[nt][2*h2]   = __expf(sacc[nt][2*h2]   - mnew);
                    sacc[nt][2*h2+1] = __expf(sacc[nt][2*h2+1] - mnew);
                    rs += sacc[nt][2*h2] + sacc[nt][2*h2+1];
                }
                rs += __shfl_xor_sync(0xffffffffu, rs, 1);
                rs += __shfl_xor_sync(0xffffffffu, rs, 2);
                l_[h2] = l_[h2] * alpha[h2] + rs;
                m_[h2] = mnew;
            }
#pragma unroll
            for (int dt = 0; dt < 8; dt++) {
                oacc[dt][0] *= alpha[0]; oacc[dt][1] *= alpha[0];
                oacc[dt][2] *= alpha[1]; oacc[dt][3] *= alpha[1];
            }

            // ---- O += Phi*Vhi + Plo*Vhi + Phi*Vlo ----
#pragma unroll
            for (int ks = 0; ks < 4; ks++) {
                uint32_t ph[4], pl[4];
                split2_pack(sacc[2*ks][0],   sacc[2*ks][1],   ph[0], pl[0]);
                split2_pack(sacc[2*ks][2],   sacc[2*ks][3],   ph[1], pl[1]);
                split2_pack(sacc[2*ks+1][0], sacc[2*ks+1][1], ph[2], pl[2]);
                split2_pack(sacc[2*ks+1][2], sacc[2*ks+1][3], ph[3], pl[3]);

                uint32_t vf[4][4];
#pragma unroll
                for (int nt2 = 0; nt2 < 4; nt2++) {
                    uint32_t addr = sVh + (uint32_t)((ks * 16 + v_row) * AST + nt2 * 16 + v_col) * 2;
                    ldsm_x4_t(vf[nt2][0], vf[nt2][1], vf[nt2][2], vf[nt2][3], addr);
                }
#pragma unroll
                for (int nt2 = 0; nt2 < 4; nt2++) {
                    mma_bf16(oacc[2*nt2],   ph[0], ph[1], ph[2], ph[3], vf[nt2][0], vf[nt2][1]);
                    mma_bf16(oacc[2*nt2+1], ph[0], ph[1], ph[2], ph[3], vf[nt2][2], vf[nt2][3]);
                    mma_bf16(oacc[2*nt2],   pl[0], pl[1], pl[2], pl[3], vf[nt2][0], vf[nt2][1]);
                    mma_bf16(oacc[2*nt2+1], pl[0], pl[1], pl[2], pl[3], vf[nt2][2], vf[nt2][3]);
                }
#pragma unroll
                for (int nt2 = 0; nt2 < 4; nt2++) {
                    uint32_t addr = sVl + (uint32_t)((ks * 16 + v_row) * AST + nt2 * 16 + v_col) * 2;
                    ldsm_x4_t(vf[nt2][0], vf[nt2][1], vf[nt2][2], vf[nt2][3], addr);
                }
#pragma unroll
                for (int nt2 = 0; nt2 < 4; nt2++) {
                    mma_bf16(oacc[2*nt2],   ph[0], ph[1], ph[2], ph[3], vf[nt2][0], vf[nt2][1]);
                    mma_bf16(oacc[2*nt2+1], ph[0], ph[1], ph[2], ph[3], vf[nt2][2], vf[nt2][3]);
                }
            }
        }
        __syncthreads();
    }

    // ---- epilogue: O/l -> g_Ac [hi|hi|lo] at rows b*1024+t, cols h*64+d ----
    const int bb = bh >> 4, hh = bh & 15;
    const float inv0 = 1.f / l_[0], inv1 = 1.f / l_[1];
#pragma unroll
    for (int dt = 0; dt < 8; dt++) {
#pragma unroll
        for (int h2 = 0; h2 < 2; h2++) {
            const int rloc = wm * 16 + (lane >> 2) + h2 * 8;
            const int d = dt * 8 + 2 * (lane & 3);
            const float inv = h2 ? inv1 : inv0;
            float ox = oacc[dt][2*h2]   * inv;
            float oy = oacc[dt][2*h2+1] * inv;
            uint32_t hw, lw;
            split2_pack(ox, oy, hw, lw);
            const size_t mrow = (size_t)(bb * T_ + q0 + rloc);
            __nv_bfloat16* row = g_Ac + mrow * KE_ + hh * 64 + d;
            *(uint32_t*)(row)          = hw;
            *(uint32_t*)(row + Cc_)    = hw;
            *(uint32_t*)(row + 2*Cc_)  = lw;
        }
    }
}

// ---------------------------------------------------------------------------
extern "C" void kernel_launch(void* const* d_in, const int* in_sizes, int n_in,
                              void* d_out, int out_size)
{
    const float* x    = (const float*)d_in[0];
    const float* Wqkv = (const float*)d_in[1];
    const float* bqkv = (const float*)d_in[2];
    const float* Wout = (const float*)d_in[3];
    const float* bout = (const float*)d_in[4];
    float* out = (float*)d_out;

    cudaFuncSetAttribute(tgemm_kernel<1>,
                         cudaFuncAttributeMaxDynamicSharedMemorySize, GSMEM_TOTAL);
    cudaFuncSetAttribute(tgemm_kernel<0>,
                         cudaFuncAttributeMaxDynamicSharedMemorySize, GSMEM_TOTAL);
    cudaFuncSetAttribute(attn_kernel,
                         cudaFuncAttributeMaxDynamicSharedMemorySize, ASMEM_TOTAL);

    // 0) split conversions
    conv_w<1><<<dim3(Cc_/32, N3_/32), 256>>>(Wqkv, N3_);
    conv_w<0><<<dim3(Cc_/32, Cc_/32), 256>>>(Wout, Cc_);
    conv_act<<<M_*Cc_/4/256, 256>>>(x);

    // 1) QKV projection -> Q/K/V bf16 hi/lo [B,H,T,D] (Q pre-scaled)
    tgemm_kernel<1><<<dim3(N3_/128, M_/128), 256, GSMEM_TOTAL>>>(bqkv, nullptr, N3_);

    // 2) HMMA causal flash attention -> g_Ac (split-expanded)
    attn_kernel<<<dim3(T_/128, BH_), 256, ASMEM_TOTAL>>>();

    // 3) output projection -> d_out
    tgemm_kernel<0><<<dim3(Cc_/128, M_/128), 256, GSMEM_TOTAL>>>(bout, out, Cc_);
}